// round 3
// baseline (speedup 1.0000x reference)
#include <cuda_runtime.h>
#include <cuda_bf16.h>

// Problem constants (fixed by reference setup_inputs)
#define BB 2
#define NN 50000
#define EE 800000
#define IN_CH 64
#define SP_CH 16
#define OUT_CH 32

// ---------------- scratch (__device__ globals; no allocation allowed) -------
__device__ __align__(16) float g_xs1[BB * NN * SP_CH];
__device__ __align__(16) float g_xd1[BB * NN * SP_CH];
__device__ __align__(16) float g_agg1[BB * NN * SP_CH];
__device__ __align__(16) float g_X1[BB * NN * SP_CH];
__device__ __align__(16) float g_xs2[BB * NN * OUT_CH];
__device__ __align__(16) float g_xd2[BB * NN * OUT_CH];
__device__ __align__(16) float g_agg2[BB * NN * OUT_CH];
// derived weights: [0:16) ka1, [16:32) qa1, [32] ewa1,
//                  [48:80) ka2, [80:112) qa2, [112] ewa2
__device__ __align__(16) float g_wder[128];

__device__ __forceinline__ float fsig(float x) {
    return __fdividef(1.0f, 1.0f + __expf(-x));
}

__device__ __forceinline__ void red4(float* p, float a, float b, float c, float d) {
    asm volatile("red.global.add.v4.f32 [%0], {%1, %2, %3, %4};"
                 :: "l"(p), "f"(a), "f"(b), "f"(c), "f"(d) : "memory");
}

// ---------------- prep: fold att_w through key/query/we ---------------------
__global__ void prep_kernel(const float* __restrict__ key1, const float* __restrict__ query1,
                            const float* __restrict__ we1, const float* __restrict__ attw1,
                            const float* __restrict__ key2, const float* __restrict__ query2,
                            const float* __restrict__ we2, const float* __restrict__ attw2) {
    int t = threadIdx.x;
    if (t < 16) {
        // layer 1: ka1[j] = sum_c key1[j,c]*aw[c]; qa1[j] = sum_c query1[j,c]*aw[16+c]
        float ka = 0.f, qa = 0.f;
        for (int c = 0; c < 16; c++) {
            ka += key1[t * 16 + c] * attw1[c];
            qa += query1[t * 16 + c] * attw1[16 + c];
        }
        g_wder[t] = ka;
        g_wder[16 + t] = qa;
    } else if (t < 48) {
        int j = t - 16;  // layer 2 rows, j in [0,32)
        float ka = 0.f, qa = 0.f;
        for (int c = 0; c < 32; c++) {
            ka += key2[j * 32 + c] * attw2[c];
            qa += query2[j * 32 + c] * attw2[32 + c];
        }
        g_wder[48 + j] = ka;
        g_wder[80 + j] = qa;
    } else if (t == 48) {
        float s = 0.f;
        for (int c = 0; c < 16; c++) s += we1[c] * attw1[32 + c];
        g_wder[32] = s;
    } else if (t == 49) {
        float s = 0.f;
        for (int c = 0; c < 32; c++) s += we2[c] * attw2[64 + c];
        g_wder[112] = s;
    }
}

// ---------------- node transforms -------------------------------------------
__global__ __launch_bounds__(256) void node1_kernel(const float* __restrict__ X,
                                                    const float* __restrict__ value1) {
    __shared__ float wv[IN_CH * SP_CH];  // 1024
    for (int i = threadIdx.x; i < IN_CH * SP_CH; i += blockDim.x) wv[i] = value1[i];
    __syncthreads();
    int t = blockIdx.x * blockDim.x + threadIdx.x;
    if (t >= BB * NN) return;
    const float4* xr = (const float4*)(X + (size_t)t * IN_CH);
    float acc[SP_CH];
#pragma unroll
    for (int c = 0; c < SP_CH; c++) acc[c] = 0.f;
#pragma unroll
    for (int j4 = 0; j4 < IN_CH / 4; j4++) {
        float4 x = xr[j4];
#pragma unroll
        for (int c = 0; c < SP_CH; c++) {
            acc[c] += x.x * wv[(j4 * 4 + 0) * SP_CH + c];
            acc[c] += x.y * wv[(j4 * 4 + 1) * SP_CH + c];
            acc[c] += x.z * wv[(j4 * 4 + 2) * SP_CH + c];
            acc[c] += x.w * wv[(j4 * 4 + 3) * SP_CH + c];
        }
    }
    float4* o = (float4*)(g_xs1 + (size_t)t * SP_CH);
#pragma unroll
    for (int k = 0; k < 4; k++)
        o[k] = make_float4(acc[4 * k], acc[4 * k + 1], acc[4 * k + 2], acc[4 * k + 3]);
}

__global__ __launch_bounds__(256) void node2_kernel(const float* __restrict__ value2) {
    __shared__ float wv[SP_CH * OUT_CH];  // 512
    for (int i = threadIdx.x; i < SP_CH * OUT_CH; i += blockDim.x) wv[i] = value2[i];
    __syncthreads();
    int t = blockIdx.x * blockDim.x + threadIdx.x;
    if (t >= BB * NN) return;
    const float4* xr = (const float4*)(g_X1 + (size_t)t * SP_CH);
    float acc[OUT_CH];
#pragma unroll
    for (int c = 0; c < OUT_CH; c++) acc[c] = 0.f;
#pragma unroll
    for (int j4 = 0; j4 < SP_CH / 4; j4++) {
        float4 x = xr[j4];
#pragma unroll
        for (int c = 0; c < OUT_CH; c++) {
            acc[c] += x.x * wv[(j4 * 4 + 0) * OUT_CH + c];
            acc[c] += x.y * wv[(j4 * 4 + 1) * OUT_CH + c];
            acc[c] += x.z * wv[(j4 * 4 + 2) * OUT_CH + c];
            acc[c] += x.w * wv[(j4 * 4 + 3) * OUT_CH + c];
        }
    }
    float4* o = (float4*)(g_xs2 + (size_t)t * OUT_CH);
#pragma unroll
    for (int k = 0; k < 8; k++)
        o[k] = make_float4(acc[4 * k], acc[4 * k + 1], acc[4 * k + 2], acc[4 * k + 3]);
}

// ---------------- gather (res_n_id) + zero aggregate -------------------------
__global__ __launch_bounds__(256) void gz1_kernel(const int* __restrict__ rn) {
    int t = blockIdx.x * blockDim.x + threadIdx.x;
    if (t >= BB * NN) return;
    int b = t / NN;
    int n = t - b * NN;
    int src = rn[n];
    const float4* srow = (const float4*)(g_xs1 + ((size_t)b * NN + src) * SP_CH);
    float4* drow = (float4*)(g_xd1 + (size_t)t * SP_CH);
    float4* arow = (float4*)(g_agg1 + (size_t)t * SP_CH);
    float4 z = make_float4(0.f, 0.f, 0.f, 0.f);
#pragma unroll
    for (int k = 0; k < 4; k++) { drow[k] = srow[k]; arow[k] = z; }
}

__global__ __launch_bounds__(256) void gz2_kernel(const int* __restrict__ rn) {
    int t = blockIdx.x * blockDim.x + threadIdx.x;
    if (t >= BB * NN) return;
    int b = t / NN;
    int n = t - b * NN;
    int src = rn[n];
    const float4* srow = (const float4*)(g_xs2 + ((size_t)b * NN + src) * OUT_CH);
    float4* drow = (float4*)(g_xd2 + (size_t)t * OUT_CH);
    float4* arow = (float4*)(g_agg2 + (size_t)t * OUT_CH);
    float4 z = make_float4(0.f, 0.f, 0.f, 0.f);
#pragma unroll
    for (int k = 0; k < 8; k++) { drow[k] = srow[k]; arow[k] = z; }
}

// ---------------- edge kernels ----------------------------------------------
__global__ __launch_bounds__(256) void edge1_kernel(const int* __restrict__ ei,
                                                    const float* __restrict__ ew,
                                                    const float* __restrict__ we,
                                                    const float* __restrict__ attb) {
    __shared__ float s_ka[16], s_qa[16], s_we[16], s_sc[2];
    if (threadIdx.x < 16) {
        s_ka[threadIdx.x] = g_wder[threadIdx.x];
        s_qa[threadIdx.x] = g_wder[16 + threadIdx.x];
        s_we[threadIdx.x] = we[threadIdx.x];
    }
    if (threadIdx.x == 0) { s_sc[0] = g_wder[32]; s_sc[1] = attb[0]; }
    __syncthreads();
    int e = blockIdx.x * blockDim.x + threadIdx.x;
    if (e >= EE) return;
    int s = ei[e];
    int d = ei[EE + e];
    float w = ew[e];
    // sigmoid(e_c) shared across batches
    float sge[16];
#pragma unroll
    for (int c = 0; c < 16; c++) sge[c] = fsig(w * s_we[c]);
    float bl = s_sc[1] + w * s_sc[0];
#pragma unroll
    for (int b = 0; b < BB; b++) {
        const float4* pj = (const float4*)(g_xs1 + ((size_t)b * NN + s) * SP_CH);
        const float4* pi = (const float4*)(g_xd1 + ((size_t)b * NN + d) * SP_CH);
        float4 xj[4];
        float logit = bl;
#pragma unroll
        for (int k = 0; k < 4; k++) {
            xj[k] = pj[k];
            float4 xi = pi[k];
            logit += xi.x * s_ka[4 * k] + xi.y * s_ka[4 * k + 1] +
                     xi.z * s_ka[4 * k + 2] + xi.w * s_ka[4 * k + 3];
            logit += xj[k].x * s_qa[4 * k] + xj[k].y * s_qa[4 * k + 1] +
                     xj[k].z * s_qa[4 * k + 2] + xj[k].w * s_qa[4 * k + 3];
        }
        float att = fsig(logit);
        float* pa = g_agg1 + ((size_t)b * NN + d) * SP_CH;
#pragma unroll
        for (int k = 0; k < 4; k++) {
            red4(pa + 4 * k,
                 att * sge[4 * k + 0] * xj[k].x,
                 att * sge[4 * k + 1] * xj[k].y,
                 att * sge[4 * k + 2] * xj[k].z,
                 att * sge[4 * k + 3] * xj[k].w);
        }
    }
}

__global__ __launch_bounds__(256) void edge2_kernel(const int* __restrict__ ei,
                                                    const float* __restrict__ ew,
                                                    const float* __restrict__ we,
                                                    const float* __restrict__ attb) {
    __shared__ float s_ka[32], s_qa[32], s_we[32], s_sc[2];
    if (threadIdx.x < 32) {
        s_ka[threadIdx.x] = g_wder[48 + threadIdx.x];
        s_qa[threadIdx.x] = g_wder[80 + threadIdx.x];
        s_we[threadIdx.x] = we[threadIdx.x];
    }
    if (threadIdx.x == 0) { s_sc[0] = g_wder[112]; s_sc[1] = attb[0]; }
    __syncthreads();
    int e = blockIdx.x * blockDim.x + threadIdx.x;
    if (e >= EE) return;
    int s = ei[e];
    int d = ei[EE + e];
    float w = ew[e];
    float sge[32];
#pragma unroll
    for (int c = 0; c < 32; c++) sge[c] = fsig(w * s_we[c]);
    float bl = s_sc[1] + w * s_sc[0];
#pragma unroll
    for (int b = 0; b < BB; b++) {
        const float4* pj = (const float4*)(g_xs2 + ((size_t)b * NN + s) * OUT_CH);
        const float4* pi = (const float4*)(g_xd2 + ((size_t)b * NN + d) * OUT_CH);
        float4 xj[8];
        float logit = bl;
#pragma unroll
        for (int k = 0; k < 8; k++) {
            xj[k] = pj[k];
            float4 xi = pi[k];
            logit += xi.x * s_ka[4 * k] + xi.y * s_ka[4 * k + 1] +
                     xi.z * s_ka[4 * k + 2] + xi.w * s_ka[4 * k + 3];
            logit += xj[k].x * s_qa[4 * k] + xj[k].y * s_qa[4 * k + 1] +
                     xj[k].z * s_qa[4 * k + 2] + xj[k].w * s_qa[4 * k + 3];
        }
        float att = fsig(logit);
        float* pa = g_agg2 + ((size_t)b * NN + d) * OUT_CH;
#pragma unroll
        for (int k = 0; k < 8; k++) {
            red4(pa + 4 * k,
                 att * sge[4 * k + 0] * xj[k].x,
                 att * sge[4 * k + 1] * xj[k].y,
                 att * sge[4 * k + 2] * xj[k].z,
                 att * sge[4 * k + 3] * xj[k].w);
        }
    }
}

// ---------------- update kernels --------------------------------------------
__global__ __launch_bounds__(256) void upd1_kernel(const float* __restrict__ cw,
                                                   const float* __restrict__ cb) {
    __shared__ float s_w[32 * 16];
    __shared__ float s_b[16];
    for (int i = threadIdx.x; i < 512; i += blockDim.x) s_w[i] = cw[i];
    if (threadIdx.x < 16) s_b[threadIdx.x] = cb[threadIdx.x];
    __syncthreads();
    int t = blockIdx.x * blockDim.x + threadIdx.x;
    if (t >= BB * NN) return;
    const float4* px = (const float4*)(g_xd1 + (size_t)t * SP_CH);
    const float4* pa = (const float4*)(g_agg1 + (size_t)t * SP_CH);
    float xd[16];
#pragma unroll
    for (int k = 0; k < 4; k++) {
        float4 v = px[k];
        xd[4 * k] = v.x; xd[4 * k + 1] = v.y; xd[4 * k + 2] = v.z; xd[4 * k + 3] = v.w;
    }
    float u[16];
#pragma unroll
    for (int c = 0; c < 16; c++) u[c] = s_b[c];
#pragma unroll
    for (int j = 0; j < 16; j++) {
#pragma unroll
        for (int c = 0; c < 16; c++) u[c] += xd[j] * s_w[j * 16 + c];
    }
#pragma unroll
    for (int k = 0; k < 4; k++) {
        float4 a = pa[k];
#pragma unroll
        for (int c = 0; c < 16; c++) {
            u[c] += a.x * s_w[(16 + 4 * k + 0) * 16 + c];
            u[c] += a.y * s_w[(16 + 4 * k + 1) * 16 + c];
            u[c] += a.z * s_w[(16 + 4 * k + 2) * 16 + c];
            u[c] += a.w * s_w[(16 + 4 * k + 3) * 16 + c];
        }
    }
    float r[16];
#pragma unroll
    for (int c = 0; c < 16; c++) {
        float v = xd[c] + fmaxf(u[c], 0.f);
        r[c] = v > 0.f ? v : 0.01f * v;  // leaky_relu
    }
    float4* o = (float4*)(g_X1 + (size_t)t * SP_CH);
#pragma unroll
    for (int k = 0; k < 4; k++)
        o[k] = make_float4(r[4 * k], r[4 * k + 1], r[4 * k + 2], r[4 * k + 3]);
}

__global__ __launch_bounds__(256) void upd2_kernel(const float* __restrict__ cw,
                                                   const float* __restrict__ cb,
                                                   float* __restrict__ out) {
    __shared__ float s_w[64 * 32];  // 8KB
    __shared__ float s_b[32];
    for (int i = threadIdx.x; i < 2048; i += blockDim.x) s_w[i] = cw[i];
    if (threadIdx.x < 32) s_b[threadIdx.x] = cb[threadIdx.x];
    __syncthreads();
    int t = blockIdx.x * blockDim.x + threadIdx.x;
    if (t >= BB * NN) return;
    const float4* px = (const float4*)(g_xd2 + (size_t)t * OUT_CH);
    const float4* pa = (const float4*)(g_agg2 + (size_t)t * OUT_CH);
    float xd[32];
#pragma unroll
    for (int k = 0; k < 8; k++) {
        float4 v = px[k];
        xd[4 * k] = v.x; xd[4 * k + 1] = v.y; xd[4 * k + 2] = v.z; xd[4 * k + 3] = v.w;
    }
    float u[32];
#pragma unroll
    for (int c = 0; c < 32; c++) u[c] = s_b[c];
#pragma unroll 8
    for (int j = 0; j < 32; j++) {
#pragma unroll
        for (int c = 0; c < 32; c++) u[c] += xd[j] * s_w[j * 32 + c];
    }
#pragma unroll
    for (int k = 0; k < 8; k++) {
        float4 a = pa[k];
#pragma unroll
        for (int c = 0; c < 32; c++) {
            u[c] += a.x * s_w[(32 + 4 * k + 0) * 32 + c];
            u[c] += a.y * s_w[(32 + 4 * k + 1) * 32 + c];
            u[c] += a.z * s_w[(32 + 4 * k + 2) * 32 + c];
            u[c] += a.w * s_w[(32 + 4 * k + 3) * 32 + c];
        }
    }
    float4* o = (float4*)(out + (size_t)t * OUT_CH);
#pragma unroll
    for (int k = 0; k < 8; k++) {
        float r0 = xd[4 * k + 0] + fmaxf(u[4 * k + 0], 0.f);
        float r1 = xd[4 * k + 1] + fmaxf(u[4 * k + 1], 0.f);
        float r2 = xd[4 * k + 2] + fmaxf(u[4 * k + 2], 0.f);
        float r3 = xd[4 * k + 3] + fmaxf(u[4 * k + 3], 0.f);
        o[k] = make_float4(r0, r1, r2, r3);
    }
}

// ---------------- launch -----------------------------------------------------
extern "C" void kernel_launch(void* const* d_in, const int* in_sizes, int n_in,
                              void* d_out, int out_size) {
    const float* X      = (const float*)d_in[0];
    const int*   ei0    = (const int*)d_in[1];
    const int*   ei1    = (const int*)d_in[2];
    const float* ew0    = (const float*)d_in[3];
    const float* ew1    = (const float*)d_in[4];
    const int*   rn0    = (const int*)d_in[5];
    const int*   rn1    = (const int*)d_in[6];
    const float* value1 = (const float*)d_in[7];
    const float* key1   = (const float*)d_in[8];
    const float* query1 = (const float*)d_in[9];
    const float* we1    = (const float*)d_in[10];
    const float* attw1  = (const float*)d_in[11];
    const float* attb1  = (const float*)d_in[12];
    const float* catw1  = (const float*)d_in[13];
    const float* catb1  = (const float*)d_in[14];
    const float* value2 = (const float*)d_in[15];
    const float* key2   = (const float*)d_in[16];
    const float* query2 = (const float*)d_in[17];
    const float* we2    = (const float*)d_in[18];
    const float* attw2  = (const float*)d_in[19];
    const float* attb2  = (const float*)d_in[20];
    const float* catw2  = (const float*)d_in[21];
    const float* catb2  = (const float*)d_in[22];
    float* out = (float*)d_out;

    const int nodeBlocks = (BB * NN + 255) / 256;
    const int edgeBlocks = (EE + 255) / 256;

    prep_kernel<<<1, 64>>>(key1, query1, we1, attw1, key2, query2, we2, attw2);
    node1_kernel<<<nodeBlocks, 256>>>(X, value1);
    gz1_kernel<<<nodeBlocks, 256>>>(rn0);
    edge1_kernel<<<edgeBlocks, 256>>>(ei0, ew0, we1, attb1);
    upd1_kernel<<<nodeBlocks, 256>>>(catw1, catb1);
    node2_kernel<<<nodeBlocks, 256>>>(value2);
    gz2_kernel<<<nodeBlocks, 256>>>(rn1);
    edge2_kernel<<<edgeBlocks, 256>>>(ei1, ew1, we2, attb2);
    upd2_kernel<<<nodeBlocks, 256>>>(catw2, catb2, out);
}

// round 5
// speedup vs baseline: 1.8917x; 1.8917x over previous
#include <cuda_runtime.h>
#include <cuda_bf16.h>

// Problem constants (fixed by reference setup_inputs)
#define BB 2
#define NN 50000
#define EE 800000
#define IN_CH 64
#define SP_CH 16
#define OUT_CH 32
#define NBN (BB * NN)

// ---------------- scratch (__device__ globals; no allocation allowed) -------
__device__ __align__(16) float g_xs1[NBN * SP_CH];
__device__ __align__(16) float g_agg1[NBN * SP_CH];
__device__ __align__(16) float g_xs2[NBN * OUT_CH];
__device__ __align__(16) float g_agg2[NBN * OUT_CH];
__device__ __align__(16) float g_ki1[NBN];
__device__ __align__(16) float g_qj1[NBN];
__device__ __align__(16) float g_ki2[NBN];
__device__ __align__(16) float g_qj2[NBN];
// derived weights: [0:16) ka1, [16:32) qa1, [32] ewa1,
//                  [48:80) ka2, [80:112) qa2, [112] ewa2
__device__ __align__(16) float g_wder[128];

__device__ __forceinline__ float fsig(float x) {
    return __fdividef(1.0f, 1.0f + __expf(-x));
}

__device__ __forceinline__ void red4(float* p, float a, float b, float c, float d) {
    asm volatile("red.global.add.v4.f32 [%0], {%1, %2, %3, %4};"
                 :: "l"(p), "f"(a), "f"(b), "f"(c), "f"(d) : "memory");
}

// ---------------- prep: fold att_w through key/query/we ---------------------
__global__ void prep_kernel(const float* __restrict__ key1, const float* __restrict__ query1,
                            const float* __restrict__ we1, const float* __restrict__ attw1,
                            const float* __restrict__ key2, const float* __restrict__ query2,
                            const float* __restrict__ we2, const float* __restrict__ attw2) {
    int t = threadIdx.x;
    if (t < 16) {
        float ka = 0.f, qa = 0.f;
        for (int c = 0; c < 16; c++) {
            ka += key1[t * 16 + c] * attw1[c];
            qa += query1[t * 16 + c] * attw1[16 + c];
        }
        g_wder[t] = ka;
        g_wder[16 + t] = qa;
    } else if (t < 48) {
        int j = t - 16;
        float ka = 0.f, qa = 0.f;
        for (int c = 0; c < 32; c++) {
            ka += key2[j * 32 + c] * attw2[c];
            qa += query2[j * 32 + c] * attw2[32 + c];
        }
        g_wder[48 + j] = ka;
        g_wder[80 + j] = qa;
    } else if (t == 48) {
        float s = 0.f;
        for (int c = 0; c < 16; c++) s += we1[c] * attw1[32 + c];
        g_wder[32] = s;
    } else if (t == 49) {
        float s = 0.f;
        for (int c = 0; c < 32; c++) s += we2[c] * attw2[64 + c];
        g_wder[112] = s;
    }
}

// ---------------- node1: xs1 = X @ value1 ------------------------------------
__global__ __launch_bounds__(256) void node1_kernel(const float* __restrict__ X,
                                                    const float* __restrict__ value1) {
    __shared__ float wv[IN_CH * SP_CH];
    for (int i = threadIdx.x; i < IN_CH * SP_CH; i += blockDim.x) wv[i] = value1[i];
    __syncthreads();
    int t = blockIdx.x * blockDim.x + threadIdx.x;
    if (t >= NBN) return;
    const float4* xr = (const float4*)(X + (size_t)t * IN_CH);
    float acc[SP_CH];
#pragma unroll
    for (int c = 0; c < SP_CH; c++) acc[c] = 0.f;
#pragma unroll
    for (int j4 = 0; j4 < IN_CH / 4; j4++) {
        float4 x = xr[j4];
#pragma unroll
        for (int c = 0; c < SP_CH; c++) {
            acc[c] += x.x * wv[(j4 * 4 + 0) * SP_CH + c];
            acc[c] += x.y * wv[(j4 * 4 + 1) * SP_CH + c];
            acc[c] += x.z * wv[(j4 * 4 + 2) * SP_CH + c];
            acc[c] += x.w * wv[(j4 * 4 + 3) * SP_CH + c];
        }
    }
    float4* o = (float4*)(g_xs1 + (size_t)t * SP_CH);
#pragma unroll
    for (int k = 0; k < 4; k++)
        o[k] = make_float4(acc[4 * k], acc[4 * k + 1], acc[4 * k + 2], acc[4 * k + 3]);
}

// ---------------- pre1: per-node scalars ki/qj + zero agg1 -------------------
__global__ __launch_bounds__(256) void pre1_kernel(const int* __restrict__ rn) {
    __shared__ float s_ka[16], s_qa[16];
    if (threadIdx.x < 16) {
        s_ka[threadIdx.x] = g_wder[threadIdx.x];
        s_qa[threadIdx.x] = g_wder[16 + threadIdx.x];
    }
    __syncthreads();
    int t = blockIdx.x * blockDim.x + threadIdx.x;
    if (t >= NBN) return;
    int b = t / NN;
    int n = t - b * NN;
    int src = rn[n];
    const float4* po = (const float4*)(g_xs1 + (size_t)t * SP_CH);
    const float4* pd = (const float4*)(g_xs1 + ((size_t)b * NN + src) * SP_CH);
    float qj = 0.f, ki = 0.f;
#pragma unroll
    for (int k = 0; k < 4; k++) {
        float4 xo = po[k];
        float4 xd = pd[k];
        qj += xo.x * s_qa[4 * k] + xo.y * s_qa[4 * k + 1] + xo.z * s_qa[4 * k + 2] + xo.w * s_qa[4 * k + 3];
        ki += xd.x * s_ka[4 * k] + xd.y * s_ka[4 * k + 1] + xd.z * s_ka[4 * k + 2] + xd.w * s_ka[4 * k + 3];
    }
    g_qj1[t] = qj;
    g_ki1[t] = ki;
    float4* arow = (float4*)(g_agg1 + (size_t)t * SP_CH);
    float4 z = make_float4(0.f, 0.f, 0.f, 0.f);
#pragma unroll
    for (int k = 0; k < 4; k++) arow[k] = z;
}

// ---------------- edge1: 4 lanes per edge ------------------------------------
__global__ __launch_bounds__(256) void edge1_kernel(const int* __restrict__ ei,
                                                    const float* __restrict__ ew,
                                                    const float* __restrict__ we,
                                                    const float* __restrict__ attb) {
    __shared__ float s_we[16], s_sc[2];
    if (threadIdx.x < 16) s_we[threadIdx.x] = we[threadIdx.x];
    if (threadIdx.x == 0) { s_sc[0] = g_wder[32]; s_sc[1] = attb[0]; }
    __syncthreads();
    int gid = blockIdx.x * blockDim.x + threadIdx.x;
    int e = gid >> 2;
    int r = gid & 3;
    if (e >= EE) return;
    int s = ei[e];
    int d = ei[EE + e];
    float w = ew[e];
    // this lane's 4 channels of sigmoid(e_c)
    float4 wec = ((const float4*)s_we)[r];
    float sg0 = fsig(w * wec.x), sg1 = fsig(w * wec.y),
          sg2 = fsig(w * wec.z), sg3 = fsig(w * wec.w);
    float bl = s_sc[1] + w * s_sc[0];
#pragma unroll
    for (int b = 0; b < BB; b++) {
        int base_s = b * NN + s;
        int base_d = b * NN + d;
        float4 xj = ((const float4*)g_xs1)[(size_t)base_s * 4 + r];
        float att = fsig(bl + g_ki1[base_d] + g_qj1[base_s]);
        red4(g_agg1 + (size_t)base_d * SP_CH + 4 * r,
             att * sg0 * xj.x, att * sg1 * xj.y,
             att * sg2 * xj.z, att * sg3 * xj.w);
    }
}

// ---------------- upd1 + node2 fused -----------------------------------------
// X1 = leaky(xd + relu(cat(xd, agg) @ cat_w1 + cb1));  xs2 = X1 @ value2
__global__ __launch_bounds__(256) void updnode2_kernel(const int* __restrict__ rn,
                                                       const float* __restrict__ cw,
                                                       const float* __restrict__ cb,
                                                       const float* __restrict__ value2) {
    __shared__ float s_w[32 * 16];
    __shared__ float s_b[16];
    __shared__ float s_v2[SP_CH * OUT_CH];
    for (int i = threadIdx.x; i < 512; i += blockDim.x) {
        s_w[i] = cw[i];
        s_v2[i] = value2[i];
    }
    if (threadIdx.x < 16) s_b[threadIdx.x] = cb[threadIdx.x];
    __syncthreads();
    int t = blockIdx.x * blockDim.x + threadIdx.x;
    if (t >= NBN) return;
    int b = t / NN;
    int n = t - b * NN;
    int src = rn[n];
    const float4* px = (const float4*)(g_xs1 + ((size_t)b * NN + src) * SP_CH);
    const float4* pa = (const float4*)(g_agg1 + (size_t)t * SP_CH);
    float xd[16];
#pragma unroll
    for (int k = 0; k < 4; k++) {
        float4 v = px[k];
        xd[4 * k] = v.x; xd[4 * k + 1] = v.y; xd[4 * k + 2] = v.z; xd[4 * k + 3] = v.w;
    }
    float u[16];
#pragma unroll
    for (int c = 0; c < 16; c++) u[c] = s_b[c];
#pragma unroll
    for (int j = 0; j < 16; j++) {
#pragma unroll
        for (int c = 0; c < 16; c++) u[c] += xd[j] * s_w[j * 16 + c];
    }
#pragma unroll
    for (int k = 0; k < 4; k++) {
        float4 a = pa[k];
#pragma unroll
        for (int c = 0; c < 16; c++) {
            u[c] += a.x * s_w[(16 + 4 * k + 0) * 16 + c];
            u[c] += a.y * s_w[(16 + 4 * k + 1) * 16 + c];
            u[c] += a.z * s_w[(16 + 4 * k + 2) * 16 + c];
            u[c] += a.w * s_w[(16 + 4 * k + 3) * 16 + c];
        }
    }
    float x1[16];
#pragma unroll
    for (int c = 0; c < 16; c++) {
        float v = xd[c] + fmaxf(u[c], 0.f);
        x1[c] = v > 0.f ? v : 0.01f * v;  // leaky_relu
    }
    // node2: xs2 = x1 @ value2  (16 -> 32)
    float acc[OUT_CH];
#pragma unroll
    for (int c = 0; c < OUT_CH; c++) acc[c] = 0.f;
#pragma unroll
    for (int j = 0; j < SP_CH; j++) {
#pragma unroll
        for (int c = 0; c < OUT_CH; c++) acc[c] += x1[j] * s_v2[j * OUT_CH + c];
    }
    float4* o = (float4*)(g_xs2 + (size_t)t * OUT_CH);
#pragma unroll
    for (int k = 0; k < 8; k++)
        o[k] = make_float4(acc[4 * k], acc[4 * k + 1], acc[4 * k + 2], acc[4 * k + 3]);
}

// ---------------- pre2 --------------------------------------------------------
__global__ __launch_bounds__(256) void pre2_kernel(const int* __restrict__ rn) {
    __shared__ float s_ka[32], s_qa[32];
    if (threadIdx.x < 32) {
        s_ka[threadIdx.x] = g_wder[48 + threadIdx.x];
        s_qa[threadIdx.x] = g_wder[80 + threadIdx.x];
    }
    __syncthreads();
    int t = blockIdx.x * blockDim.x + threadIdx.x;
    if (t >= NBN) return;
    int b = t / NN;
    int n = t - b * NN;
    int src = rn[n];
    const float4* po = (const float4*)(g_xs2 + (size_t)t * OUT_CH);
    const float4* pd = (const float4*)(g_xs2 + ((size_t)b * NN + src) * OUT_CH);
    float qj = 0.f, ki = 0.f;
#pragma unroll
    for (int k = 0; k < 8; k++) {
        float4 xo = po[k];
        float4 xd = pd[k];
        qj += xo.x * s_qa[4 * k] + xo.y * s_qa[4 * k + 1] + xo.z * s_qa[4 * k + 2] + xo.w * s_qa[4 * k + 3];
        ki += xd.x * s_ka[4 * k] + xd.y * s_ka[4 * k + 1] + xd.z * s_ka[4 * k + 2] + xd.w * s_ka[4 * k + 3];
    }
    g_qj2[t] = qj;
    g_ki2[t] = ki;
    float4* arow = (float4*)(g_agg2 + (size_t)t * OUT_CH);
    float4 z = make_float4(0.f, 0.f, 0.f, 0.f);
#pragma unroll
    for (int k = 0; k < 8; k++) arow[k] = z;
}

// ---------------- edge2: 8 lanes per edge ------------------------------------
__global__ __launch_bounds__(256) void edge2_kernel(const int* __restrict__ ei,
                                                    const float* __restrict__ ew,
                                                    const float* __restrict__ we,
                                                    const float* __restrict__ attb) {
    __shared__ float s_we[32], s_sc[2];
    if (threadIdx.x < 32) s_we[threadIdx.x] = we[threadIdx.x];
    if (threadIdx.x == 0) { s_sc[0] = g_wder[112]; s_sc[1] = attb[0]; }
    __syncthreads();
    int gid = blockIdx.x * blockDim.x + threadIdx.x;
    int e = gid >> 3;
    int r = gid & 7;
    if (e >= EE) return;
    int s = ei[e];
    int d = ei[EE + e];
    float w = ew[e];
    float4 wec = ((const float4*)s_we)[r];
    float sg0 = fsig(w * wec.x), sg1 = fsig(w * wec.y),
          sg2 = fsig(w * wec.z), sg3 = fsig(w * wec.w);
    float bl = s_sc[1] + w * s_sc[0];
#pragma unroll
    for (int b = 0; b < BB; b++) {
        int base_s = b * NN + s;
        int base_d = b * NN + d;
        float4 xj = ((const float4*)g_xs2)[(size_t)base_s * 8 + r];
        float att = fsig(bl + g_ki2[base_d] + g_qj2[base_s]);
        red4(g_agg2 + (size_t)base_d * OUT_CH + 4 * r,
             att * sg0 * xj.x, att * sg1 * xj.y,
             att * sg2 * xj.z, att * sg3 * xj.w);
    }
}

// ---------------- upd2: final output -----------------------------------------
__global__ __launch_bounds__(256) void upd2_kernel(const int* __restrict__ rn,
                                                   const float* __restrict__ cw,
                                                   const float* __restrict__ cb,
                                                   float* __restrict__ out) {
    __shared__ float s_w[64 * 32];  // 8KB
    __shared__ float s_b[32];
    for (int i = threadIdx.x; i < 2048; i += blockDim.x) s_w[i] = cw[i];
    if (threadIdx.x < 32) s_b[threadIdx.x] = cb[threadIdx.x];
    __syncthreads();
    int t = blockIdx.x * blockDim.x + threadIdx.x;
    if (t >= NBN) return;
    int b = t / NN;
    int n = t - b * NN;
    int src = rn[n];
    const float4* px = (const float4*)(g_xs2 + ((size_t)b * NN + src) * OUT_CH);
    const float4* pa = (const float4*)(g_agg2 + (size_t)t * OUT_CH);
    float xd[32];
#pragma unroll
    for (int k = 0; k < 8; k++) {
        float4 v = px[k];
        xd[4 * k] = v.x; xd[4 * k + 1] = v.y; xd[4 * k + 2] = v.z; xd[4 * k + 3] = v.w;
    }
    float u[32];
#pragma unroll
    for (int c = 0; c < 32; c++) u[c] = s_b[c];
#pragma unroll 8
    for (int j = 0; j < 32; j++) {
#pragma unroll
        for (int c = 0; c < 32; c++) u[c] += xd[j] * s_w[j * 32 + c];
    }
#pragma unroll
    for (int k = 0; k < 8; k++) {
        float4 a = pa[k];
#pragma unroll
        for (int c = 0; c < 32; c++) {
            u[c] += a.x * s_w[(32 + 4 * k + 0) * 32 + c];
            u[c] += a.y * s_w[(32 + 4 * k + 1) * 32 + c];
            u[c] += a.z * s_w[(32 + 4 * k + 2) * 32 + c];
            u[c] += a.w * s_w[(32 + 4 * k + 3) * 32 + c];
        }
    }
    float4* o = (float4*)(out + (size_t)t * OUT_CH);
#pragma unroll
    for (int k = 0; k < 8; k++) {
        float r0 = xd[4 * k + 0] + fmaxf(u[4 * k + 0], 0.f);
        float r1 = xd[4 * k + 1] + fmaxf(u[4 * k + 1], 0.f);
        float r2 = xd[4 * k + 2] + fmaxf(u[4 * k + 2], 0.f);
        float r3 = xd[4 * k + 3] + fmaxf(u[4 * k + 3], 0.f);
        o[k] = make_float4(r0, r1, r2, r3);
    }
}

// ---------------- launch -----------------------------------------------------
extern "C" void kernel_launch(void* const* d_in, const int* in_sizes, int n_in,
                              void* d_out, int out_size) {
    const float* X      = (const float*)d_in[0];
    const int*   ei0    = (const int*)d_in[1];
    const int*   ei1    = (const int*)d_in[2];
    const float* ew0    = (const float*)d_in[3];
    const float* ew1    = (const float*)d_in[4];
    const int*   rn0    = (const int*)d_in[5];
    const int*   rn1    = (const int*)d_in[6];
    const float* value1 = (const float*)d_in[7];
    const float* key1   = (const float*)d_in[8];
    const float* query1 = (const float*)d_in[9];
    const float* we1    = (const float*)d_in[10];
    const float* attw1  = (const float*)d_in[11];
    const float* attb1  = (const float*)d_in[12];
    const float* catw1  = (const float*)d_in[13];
    const float* catb1  = (const float*)d_in[14];
    const float* value2 = (const float*)d_in[15];
    const float* key2   = (const float*)d_in[16];
    const float* query2 = (const float*)d_in[17];
    const float* we2    = (const float*)d_in[18];
    const float* attw2  = (const float*)d_in[19];
    const float* attb2  = (const float*)d_in[20];
    const float* catw2  = (const float*)d_in[21];
    const float* catb2  = (const float*)d_in[22];
    float* out = (float*)d_out;

    const int nodeBlocks  = (NBN + 255) / 256;
    const int edge1Blocks = (EE * 4 + 255) / 256;
    const int edge2Blocks = (EE * 8 + 255) / 256;

    prep_kernel<<<1, 64>>>(key1, query1, we1, attw1, key2, query2, we2, attw2);
    node1_kernel<<<nodeBlocks, 256>>>(X, value1);
    pre1_kernel<<<nodeBlocks, 256>>>(rn0);
    edge1_kernel<<<edge1Blocks, 256>>>(ei0, ew0, we1, attb1);
    updnode2_kernel<<<nodeBlocks, 256>>>(rn0, catw1, catb1, value2);
    pre2_kernel<<<nodeBlocks, 256>>>(rn1);
    edge2_kernel<<<edge2Blocks, 256>>>(ei1, ew1, we2, attb2);
    upd2_kernel<<<nodeBlocks, 256>>>(rn1, catw2, catb2, out);
}

// round 7
// speedup vs baseline: 2.1096x; 1.1152x over previous
#include <cuda_runtime.h>
#include <cuda_bf16.h>

// Problem constants (fixed by reference setup_inputs)
#define BB 2
#define NN 50000
#define EE 800000
#define IN_CH 64
#define SP_CH 16
#define OUT_CH 32
#define NBN (BB * NN)

// ---------------- scratch: batch-interleaved layouts [n][b][ch] --------------
__device__ __align__(128) float g_xs1[NN * BB * SP_CH];
__device__ __align__(128) float g_agg1[NN * BB * SP_CH];
__device__ __align__(128) float g_xs2[NN * BB * OUT_CH];
__device__ __align__(128) float g_agg2[NN * BB * OUT_CH];
// per-(node,batch) scalars, interleaved [n][b]
__device__ __align__(16) float g_qj1[NN * BB];
__device__ __align__(16) float g_ks1[NN * BB];
__device__ __align__(16) float g_ki1[NN * BB];
__device__ __align__(16) float g_qj2[NN * BB];
__device__ __align__(16) float g_ks2[NN * BB];
__device__ __align__(16) float g_ki2[NN * BB];
// derived weights: [0:16) ka1, [16:32) qa1, [32] ewa1,
//                  [48:80) ka2, [80:112) qa2, [112] ewa2
__device__ __align__(16) float g_wder[128];

__device__ __forceinline__ float fsig(float x) {
    return __fdividef(1.0f, 1.0f + __expf(-x));
}

__device__ __forceinline__ void red4(float* p, float a, float b, float c, float d) {
    asm volatile("red.global.add.v4.f32 [%0], {%1, %2, %3, %4};"
                 :: "l"(p), "f"(a), "f"(b), "f"(c), "f"(d) : "memory");
}

// ---------------- prep: fold att_w through key/query/we ---------------------
__global__ void prep_kernel(const float* __restrict__ key1, const float* __restrict__ query1,
                            const float* __restrict__ we1, const float* __restrict__ attw1,
                            const float* __restrict__ key2, const float* __restrict__ query2,
                            const float* __restrict__ we2, const float* __restrict__ attw2) {
    int t = threadIdx.x;
    if (t < 16) {
        float ka = 0.f, qa = 0.f;
        for (int c = 0; c < 16; c++) {
            ka += key1[t * 16 + c] * attw1[c];
            qa += query1[t * 16 + c] * attw1[16 + c];
        }
        g_wder[t] = ka;
        g_wder[16 + t] = qa;
    } else if (t < 48) {
        int j = t - 16;
        float ka = 0.f, qa = 0.f;
        for (int c = 0; c < 32; c++) {
            ka += key2[j * 32 + c] * attw2[c];
            qa += query2[j * 32 + c] * attw2[32 + c];
        }
        g_wder[48 + j] = ka;
        g_wder[80 + j] = qa;
    } else if (t == 48) {
        float s = 0.f;
        for (int c = 0; c < 16; c++) s += we1[c] * attw1[32 + c];
        g_wder[32] = s;
    } else if (t == 49) {
        float s = 0.f;
        for (int c = 0; c < 32; c++) s += we2[c] * attw2[64 + c];
        g_wder[112] = s;
    }
}

// ---------------- node1: one thread per (n,b) row ----------------------------
// xs1[n][b] = X[b][n] @ value1 ; also qj1/ks1 scalars and zero agg1
__global__ __launch_bounds__(256) void node1_kernel(const float* __restrict__ X,
                                                    const float* __restrict__ value1) {
    __shared__ float wv[IN_CH * SP_CH];
    __shared__ float s_ka[16], s_qa[16];
    for (int i = threadIdx.x; i < IN_CH * SP_CH; i += blockDim.x) wv[i] = value1[i];
    if (threadIdx.x < 16) {
        s_ka[threadIdx.x] = g_wder[threadIdx.x];
        s_qa[threadIdx.x] = g_wder[16 + threadIdx.x];
    }
    __syncthreads();
    int t = blockIdx.x * blockDim.x + threadIdx.x;
    if (t >= NBN) return;
    int n = t / BB;
    int b = t - n * BB;
    const float4* xr = (const float4*)(X + ((size_t)b * NN + n) * IN_CH);
    float acc[SP_CH];
#pragma unroll
    for (int c = 0; c < SP_CH; c++) acc[c] = 0.f;
#pragma unroll
    for (int j4 = 0; j4 < IN_CH / 4; j4++) {
        float4 x = xr[j4];
#pragma unroll
        for (int c = 0; c < SP_CH; c++) {
            acc[c] += x.x * wv[(j4 * 4 + 0) * SP_CH + c];
            acc[c] += x.y * wv[(j4 * 4 + 1) * SP_CH + c];
            acc[c] += x.z * wv[(j4 * 4 + 2) * SP_CH + c];
            acc[c] += x.w * wv[(j4 * 4 + 3) * SP_CH + c];
        }
    }
    float4* o = (float4*)(g_xs1 + (size_t)t * SP_CH);
    float4* az = (float4*)(g_agg1 + (size_t)t * SP_CH);
    float4 z = make_float4(0.f, 0.f, 0.f, 0.f);
    float qj = 0.f, ks = 0.f;
#pragma unroll
    for (int k = 0; k < 4; k++) {
        o[k] = make_float4(acc[4 * k], acc[4 * k + 1], acc[4 * k + 2], acc[4 * k + 3]);
        az[k] = z;
#pragma unroll
        for (int j = 0; j < 4; j++) {
            qj += acc[4 * k + j] * s_qa[4 * k + j];
            ks += acc[4 * k + j] * s_ka[4 * k + j];
        }
    }
    g_qj1[t] = qj;
    g_ks1[t] = ks;
}

// ---------------- pre1: scalar gather ki = ks[rn[n]] -------------------------
__global__ __launch_bounds__(256) void pre1_kernel(const int* __restrict__ rn) {
    int n = blockIdx.x * blockDim.x + threadIdx.x;
    if (n >= NN) return;
    int src = rn[n];
    *(float2*)(g_ki1 + (size_t)n * BB) = *(const float2*)(g_ks1 + (size_t)src * BB);
}

// ---------------- edge1: 4 lanes per edge ------------------------------------
__global__ __launch_bounds__(256) void edge1_kernel(const int* __restrict__ ei,
                                                    const float* __restrict__ ew,
                                                    const float* __restrict__ we,
                                                    const float* __restrict__ attb) {
    __shared__ float s_we[16], s_sc[2];
    if (threadIdx.x < 16) s_we[threadIdx.x] = we[threadIdx.x];
    if (threadIdx.x == 0) { s_sc[0] = g_wder[32]; s_sc[1] = attb[0]; }
    __syncthreads();
    int gid = blockIdx.x * blockDim.x + threadIdx.x;
    int e = gid >> 2;
    int r = gid & 3;
    if (e >= EE) return;
    int s = ei[e];
    int d = ei[EE + e];
    float w = ew[e];
    float4 wec = ((const float4*)s_we)[r];
    float sg0 = fsig(w * wec.x), sg1 = fsig(w * wec.y),
          sg2 = fsig(w * wec.z), sg3 = fsig(w * wec.w);
    float bl = s_sc[1] + w * s_sc[0];
    float2 ki = *(const float2*)(g_ki1 + (size_t)d * BB);
    float2 qj = *(const float2*)(g_qj1 + (size_t)s * BB);
    float att0 = fsig(bl + ki.x + qj.x);
    float att1 = fsig(bl + ki.y + qj.y);
    const float4* xsrow = (const float4*)(g_xs1 + (size_t)s * BB * SP_CH);
    float* aggrow = g_agg1 + (size_t)d * BB * SP_CH;
    {
        float4 xj = xsrow[r];
        red4(aggrow + 4 * r,
             att0 * sg0 * xj.x, att0 * sg1 * xj.y,
             att0 * sg2 * xj.z, att0 * sg3 * xj.w);
    }
    {
        float4 xj = xsrow[4 + r];
        red4(aggrow + SP_CH + 4 * r,
             att1 * sg0 * xj.x, att1 * sg1 * xj.y,
             att1 * sg2 * xj.z, att1 * sg3 * xj.w);
    }
}

// ---------------- upd1 + node2 fused: one thread per (n,b) row ---------------
__global__ __launch_bounds__(256) void updnode2_kernel(const int* __restrict__ rn,
                                                       const float* __restrict__ cw,
                                                       const float* __restrict__ cb,
                                                       const float* __restrict__ value2) {
    __shared__ float s_w[32 * 16];
    __shared__ float s_b[16];
    __shared__ float s_v2[SP_CH * OUT_CH];
    __shared__ float s_ka[32], s_qa[32];
    for (int i = threadIdx.x; i < 512; i += blockDim.x) {
        s_w[i] = cw[i];
        s_v2[i] = value2[i];
    }
    if (threadIdx.x < 16) s_b[threadIdx.x] = cb[threadIdx.x];
    if (threadIdx.x < 32) {
        s_ka[threadIdx.x] = g_wder[48 + threadIdx.x];
        s_qa[threadIdx.x] = g_wder[80 + threadIdx.x];
    }
    __syncthreads();
    int t = blockIdx.x * blockDim.x + threadIdx.x;
    if (t >= NBN) return;
    int n = t / BB;
    int b = t - n * BB;
    int src = rn[n];
    const float4* px = (const float4*)(g_xs1 + ((size_t)src * BB + b) * SP_CH);
    const float4* pa = (const float4*)(g_agg1 + (size_t)t * SP_CH);
    float xd[16];
#pragma unroll
    for (int k = 0; k < 4; k++) {
        float4 v = px[k];
        xd[4 * k] = v.x; xd[4 * k + 1] = v.y; xd[4 * k + 2] = v.z; xd[4 * k + 3] = v.w;
    }
    float u[16];
#pragma unroll
    for (int c = 0; c < 16; c++) u[c] = s_b[c];
#pragma unroll
    for (int j = 0; j < 16; j++) {
#pragma unroll
        for (int c = 0; c < 16; c++) u[c] += xd[j] * s_w[j * 16 + c];
    }
#pragma unroll
    for (int k = 0; k < 4; k++) {
        float4 a = pa[k];
#pragma unroll
        for (int c = 0; c < 16; c++) {
            u[c] += a.x * s_w[(16 + 4 * k + 0) * 16 + c];
            u[c] += a.y * s_w[(16 + 4 * k + 1) * 16 + c];
            u[c] += a.z * s_w[(16 + 4 * k + 2) * 16 + c];
            u[c] += a.w * s_w[(16 + 4 * k + 3) * 16 + c];
        }
    }
    float x1[16];
#pragma unroll
    for (int c = 0; c < 16; c++) {
        float v = xd[c] + fmaxf(u[c], 0.f);
        x1[c] = v > 0.f ? v : 0.01f * v;  // leaky_relu
    }
    // node2: xs2 = x1 @ value2 (16 -> 32)
    float acc[OUT_CH];
#pragma unroll
    for (int c = 0; c < OUT_CH; c++) acc[c] = 0.f;
#pragma unroll
    for (int j = 0; j < SP_CH; j++) {
#pragma unroll
        for (int c = 0; c < OUT_CH; c++) acc[c] += x1[j] * s_v2[j * OUT_CH + c];
    }
    float4* o = (float4*)(g_xs2 + (size_t)t * OUT_CH);
    float4* az = (float4*)(g_agg2 + (size_t)t * OUT_CH);
    float4 z = make_float4(0.f, 0.f, 0.f, 0.f);
    float qj = 0.f, ks = 0.f;
#pragma unroll
    for (int k = 0; k < 8; k++) {
        o[k] = make_float4(acc[4 * k], acc[4 * k + 1], acc[4 * k + 2], acc[4 * k + 3]);
        az[k] = z;
#pragma unroll
        for (int j = 0; j < 4; j++) {
            qj += acc[4 * k + j] * s_qa[4 * k + j];
            ks += acc[4 * k + j] * s_ka[4 * k + j];
        }
    }
    g_qj2[t] = qj;
    g_ks2[t] = ks;
}

// ---------------- pre2: scalar gather ----------------------------------------
__global__ __launch_bounds__(256) void pre2_kernel(const int* __restrict__ rn) {
    int n = blockIdx.x * blockDim.x + threadIdx.x;
    if (n >= NN) return;
    int src = rn[n];
    *(float2*)(g_ki2 + (size_t)n * BB) = *(const float2*)(g_ks2 + (size_t)src * BB);
}

// ---------------- edge2: 8 lanes per edge ------------------------------------
__global__ __launch_bounds__(256) void edge2_kernel(const int* __restrict__ ei,
                                                    const float* __restrict__ ew,
                                                    const float* __restrict__ we,
                                                    const float* __restrict__ attb) {
    __shared__ float s_we[32], s_sc[2];
    if (threadIdx.x < 32) s_we[threadIdx.x] = we[threadIdx.x];
    if (threadIdx.x == 0) { s_sc[0] = g_wder[112]; s_sc[1] = attb[0]; }
    __syncthreads();
    int gid = blockIdx.x * blockDim.x + threadIdx.x;
    int e = gid >> 3;
    int r = gid & 7;
    if (e >= EE) return;
    int s = ei[e];
    int d = ei[EE + e];
    float w = ew[e];
    float4 wec = ((const float4*)s_we)[r];
    float sg0 = fsig(w * wec.x), sg1 = fsig(w * wec.y),
          sg2 = fsig(w * wec.z), sg3 = fsig(w * wec.w);
    float bl = s_sc[1] + w * s_sc[0];
    float2 ki = *(const float2*)(g_ki2 + (size_t)d * BB);
    float2 qj = *(const float2*)(g_qj2 + (size_t)s * BB);
    float att0 = fsig(bl + ki.x + qj.x);
    float att1 = fsig(bl + ki.y + qj.y);
    const float4* xsrow = (const float4*)(g_xs2 + (size_t)s * BB * OUT_CH);
    float* aggrow = g_agg2 + (size_t)d * BB * OUT_CH;
    {
        float4 xj = xsrow[r];
        red4(aggrow + 4 * r,
             att0 * sg0 * xj.x, att0 * sg1 * xj.y,
             att0 * sg2 * xj.z, att0 * sg3 * xj.w);
    }
    {
        float4 xj = xsrow[8 + r];
        red4(aggrow + OUT_CH + 4 * r,
             att1 * sg0 * xj.x, att1 * sg1 * xj.y,
             att1 * sg2 * xj.z, att1 * sg3 * xj.w);
    }
}

// ---------------- upd2: one thread per (n,b); output [b][n][32] --------------
__global__ __launch_bounds__(256) void upd2_kernel(const int* __restrict__ rn,
                                                   const float* __restrict__ cw,
                                                   const float* __restrict__ cb,
                                                   float* __restrict__ out) {
    __shared__ float s_w[64 * 32];  // 8KB
    __shared__ float s_b[32];
    for (int i = threadIdx.x; i < 2048; i += blockDim.x) s_w[i] = cw[i];
    if (threadIdx.x < 32) s_b[threadIdx.x] = cb[threadIdx.x];
    __syncthreads();
    int t = blockIdx.x * blockDim.x + threadIdx.x;
    if (t >= NBN) return;
    int n = t / BB;
    int b = t - n * BB;
    int src = rn[n];
    const float4* px = (const float4*)(g_xs2 + ((size_t)src * BB + b) * OUT_CH);
    const float4* pa = (const float4*)(g_agg2 + (size_t)t * OUT_CH);
    float xd[32];
#pragma unroll
    for (int k = 0; k < 8; k++) {
        float4 v = px[k];
        xd[4 * k] = v.x; xd[4 * k + 1] = v.y; xd[4 * k + 2] = v.z; xd[4 * k + 3] = v.w;
    }
    float u[32];
#pragma unroll
    for (int c = 0; c < 32; c++) u[c] = s_b[c];
#pragma unroll 8
    for (int j = 0; j < 32; j++) {
#pragma unroll
        for (int c = 0; c < 32; c++) u[c] += xd[j] * s_w[j * 32 + c];
    }
#pragma unroll
    for (int k = 0; k < 8; k++) {
        float4 a = pa[k];
#pragma unroll
        for (int c = 0; c < 32; c++) {
            u[c] += a.x * s_w[(32 + 4 * k + 0) * 32 + c];
            u[c] += a.y * s_w[(32 + 4 * k + 1) * 32 + c];
            u[c] += a.z * s_w[(32 + 4 * k + 2) * 32 + c];
            u[c] += a.w * s_w[(32 + 4 * k + 3) * 32 + c];
        }
    }
    float4* o = (float4*)(out + ((size_t)b * NN + n) * OUT_CH);
#pragma unroll
    for (int k = 0; k < 8; k++) {
        float r0 = xd[4 * k + 0] + fmaxf(u[4 * k + 0], 0.f);
        float r1 = xd[4 * k + 1] + fmaxf(u[4 * k + 1], 0.f);
        float r2 = xd[4 * k + 2] + fmaxf(u[4 * k + 2], 0.f);
        float r3 = xd[4 * k + 3] + fmaxf(u[4 * k + 3], 0.f);
        o[k] = make_float4(r0, r1, r2, r3);
    }
}

// ---------------- launch -----------------------------------------------------
extern "C" void kernel_launch(void* const* d_in, const int* in_sizes, int n_in,
                              void* d_out, int out_size) {
    const float* X      = (const float*)d_in[0];
    const int*   ei0    = (const int*)d_in[1];
    const int*   ei1    = (const int*)d_in[2];
    const float* ew0    = (const float*)d_in[3];
    const float* ew1    = (const float*)d_in[4];
    const int*   rn0    = (const int*)d_in[5];
    const int*   rn1    = (const int*)d_in[6];
    const float* value1 = (const float*)d_in[7];
    const float* key1   = (const float*)d_in[8];
    const float* query1 = (const float*)d_in[9];
    const float* we1    = (const float*)d_in[10];
    const float* attw1  = (const float*)d_in[11];
    const float* attb1  = (const float*)d_in[12];
    const float* catw1  = (const float*)d_in[13];
    const float* catb1  = (const float*)d_in[14];
    const float* value2 = (const float*)d_in[15];
    const float* key2   = (const float*)d_in[16];
    const float* query2 = (const float*)d_in[17];
    const float* we2    = (const float*)d_in[18];
    const float* attw2  = (const float*)d_in[19];
    const float* attb2  = (const float*)d_in[20];
    const float* catw2  = (const float*)d_in[21];
    const float* catb2  = (const float*)d_in[22];
    float* out = (float*)d_out;

    const int rowBlocks   = (NBN + 255) / 256;
    const int nBlocks     = (NN + 255) / 256;
    const int edge1Blocks = (EE * 4 + 255) / 256;
    const int edge2Blocks = (EE * 8 + 255) / 256;

    prep_kernel<<<1, 64>>>(key1, query1, we1, attw1, key2, query2, we2, attw2);
    node1_kernel<<<rowBlocks, 256>>>(X, value1);
    pre1_kernel<<<nBlocks, 256>>>(rn0);
    edge1_kernel<<<edge1Blocks, 256>>>(ei0, ew0, we1, attb1);
    updnode2_kernel<<<rowBlocks, 256>>>(rn0, catw1, catb1, value2);
    pre2_kernel<<<nBlocks, 256>>>(rn1);
    edge2_kernel<<<edge2Blocks, 256>>>(ei1, ew1, we2, attb2);
    upd2_kernel<<<rowBlocks, 256>>>(rn1, catw2, catb2, out);
}

// round 11
// speedup vs baseline: 2.1310x; 1.0101x over previous
#include <cuda_runtime.h>
#include <cuda_bf16.h>

// Problem constants (fixed by reference setup_inputs)
#define BB 2
#define NN 50000
#define EE 800000
#define IN_CH 64
#define SP_CH 16
#define OUT_CH 32
#define NBN (BB * NN)

// ---------------- scratch: batch-interleaved layouts [n][b][ch] --------------
__device__ __align__(128) float g_xs1[NN * BB * SP_CH];
__device__ __align__(128) float g_agg1[NN * BB * SP_CH];
__device__ __align__(128) float g_xs2[NN * BB * OUT_CH];
__device__ __align__(128) float g_agg2[NN * BB * OUT_CH];
// per-(node,batch) scalars, interleaved [n][b]
__device__ __align__(16) float g_qj1[NN * BB];
__device__ __align__(16) float g_ks1[NN * BB];
__device__ __align__(16) float g_ki1[NN * BB];
__device__ __align__(16) float g_qj2[NN * BB];
__device__ __align__(16) float g_ks2[NN * BB];
__device__ __align__(16) float g_ki2[NN * BB];
// derived weights: [0:16) ka1, [16:32) qa1, [32] ewa1,
//                  [48:80) ka2, [80:112) qa2, [112] ewa2
__device__ __align__(16) float g_wder[128];

// sigmoid via single-MUFU tanh.approx: sig(x) = 0.5*tanh(x/2) + 0.5
__device__ __forceinline__ float fsig(float x) {
    float t;
    asm("tanh.approx.f32 %0, %1;" : "=f"(t) : "f"(0.5f * x));
    return fmaf(0.5f, t, 0.5f);
}

__device__ __forceinline__ void red4(float* p, float a, float b, float c, float d) {
    asm volatile("red.global.add.v4.f32 [%0], {%1, %2, %3, %4};"
                 :: "l"(p), "f"(a), "f"(b), "f"(c), "f"(d) : "memory");
}

// ---------------- prep: fold att_w through key/query/we ---------------------
__global__ void prep_kernel(const float* __restrict__ key1, const float* __restrict__ query1,
                            const float* __restrict__ we1, const float* __restrict__ attw1,
                            const float* __restrict__ key2, const float* __restrict__ query2,
                            const float* __restrict__ we2, const float* __restrict__ attw2) {
    int t = threadIdx.x;
    if (t < 16) {
        float ka = 0.f, qa = 0.f;
        for (int c = 0; c < 16; c++) {
            ka += key1[t * 16 + c] * attw1[c];
            qa += query1[t * 16 + c] * attw1[16 + c];
        }
        g_wder[t] = ka;
        g_wder[16 + t] = qa;
    } else if (t < 48) {
        int j = t - 16;
        float ka = 0.f, qa = 0.f;
        for (int c = 0; c < 32; c++) {
            ka += key2[j * 32 + c] * attw2[c];
            qa += query2[j * 32 + c] * attw2[32 + c];
        }
        g_wder[48 + j] = ka;
        g_wder[80 + j] = qa;
    } else if (t == 48) {
        float s = 0.f;
        for (int c = 0; c < 16; c++) s += we1[c] * attw1[32 + c];
        g_wder[32] = s;
    } else if (t == 49) {
        float s = 0.f;
        for (int c = 0; c < 32; c++) s += we2[c] * attw2[64 + c];
        g_wder[112] = s;
    }
}

// ---------------- node1: smem-staged X, per-thread-row compute ---------------
// Block = 256 rows. X staged in 4 column-chunks; outputs staged for coalescing.
__global__ __launch_bounds__(256) void node1_kernel(const float* __restrict__ X,
                                                    const float* __restrict__ value1) {
    __shared__ float wv[IN_CH * SP_CH];        // 4KB
    __shared__ float s_ka[16], s_qa[16];
    __shared__ float4 s_tile[256 * 5];         // 20KB, padded stride 5 float4/row
    for (int i = threadIdx.x; i < IN_CH * SP_CH; i += blockDim.x) wv[i] = value1[i];
    if (threadIdx.x < 16) {
        s_ka[threadIdx.x] = g_wder[threadIdx.x];
        s_qa[threadIdx.x] = g_wder[16 + threadIdx.x];
    }
    int tid = threadIdx.x;
    int blockRow0 = blockIdx.x * 256;
    int t = blockRow0 + tid;

    float acc[SP_CH];
#pragma unroll
    for (int c = 0; c < SP_CH; c++) acc[c] = 0.f;

    __syncthreads();
#pragma unroll
    for (int kc = 0; kc < 4; kc++) {
        // ---- coalesced staged load of X[:, kc*16 : kc*16+16] for 256 rows ----
#pragma unroll
        for (int p = 0; p < 4; p++) {
            int i = p * 256 + tid;
            int r = i >> 2, c4 = i & 3;
            int gRow = blockRow0 + r;
            float4 v = make_float4(0.f, 0.f, 0.f, 0.f);
            if (gRow < NBN) {
                int n = gRow >> 1, b = gRow & 1;
                v = *(const float4*)(X + ((size_t)b * NN + n) * IN_CH + kc * 16 + c4 * 4);
            }
            s_tile[r * 5 + c4] = v;
        }
        __syncthreads();
        // ---- per-thread compute from smem row ----
        float4 xk[4];
#pragma unroll
        for (int j = 0; j < 4; j++) xk[j] = s_tile[tid * 5 + j];
#pragma unroll
        for (int j = 0; j < 4; j++) {
            int jg = kc * 16 + j * 4;
#pragma unroll
            for (int c = 0; c < SP_CH; c++) {
                acc[c] += xk[j].x * wv[(jg + 0) * SP_CH + c];
                acc[c] += xk[j].y * wv[(jg + 1) * SP_CH + c];
                acc[c] += xk[j].z * wv[(jg + 2) * SP_CH + c];
                acc[c] += xk[j].w * wv[(jg + 3) * SP_CH + c];
            }
        }
        __syncthreads();
    }
    // scalars (coalesced 4B stores)
    if (t < NBN) {
        float qj = 0.f, ks = 0.f;
#pragma unroll
        for (int c = 0; c < SP_CH; c++) {
            qj += acc[c] * s_qa[c];
            ks += acc[c] * s_ka[c];
        }
        g_qj1[t] = qj;
        g_ks1[t] = ks;
    }
    // ---- staged coalesced store of xs1 (and flat agg1 zero) ----
#pragma unroll
    for (int j = 0; j < 4; j++)
        s_tile[tid * 5 + j] = make_float4(acc[4 * j], acc[4 * j + 1], acc[4 * j + 2], acc[4 * j + 3]);
    __syncthreads();
    float4 z = make_float4(0.f, 0.f, 0.f, 0.f);
#pragma unroll
    for (int p = 0; p < 4; p++) {
        int i = p * 256 + tid;
        int r = i >> 2, c4 = i & 3;
        int gRow = blockRow0 + r;
        if (gRow < NBN) {
            ((float4*)g_xs1)[(size_t)gRow * 4 + c4] = s_tile[r * 5 + c4];
            ((float4*)g_agg1)[(size_t)gRow * 4 + c4] = z;
        }
    }
}

// ---------------- pre1: scalar gather ki = ks[rn[n]] -------------------------
__global__ __launch_bounds__(256) void pre1_kernel(const int* __restrict__ rn) {
    int n = blockIdx.x * blockDim.x + threadIdx.x;
    if (n >= NN) return;
    int src = rn[n];
    *(float2*)(g_ki1 + (size_t)n * BB) = *(const float2*)(g_ks1 + (size_t)src * BB);
}

// ---------------- edge1: 8 lanes per edge (one load, one red) ----------------
__global__ __launch_bounds__(256) void edge1_kernel(const int* __restrict__ ei,
                                                    const float* __restrict__ ew,
                                                    const float* __restrict__ we,
                                                    const float* __restrict__ attb) {
    __shared__ float s_we[16], s_sc[2];
    if (threadIdx.x < 16) s_we[threadIdx.x] = we[threadIdx.x];
    if (threadIdx.x == 0) { s_sc[0] = g_wder[32]; s_sc[1] = attb[0]; }
    __syncthreads();
    int gid = blockIdx.x * blockDim.x + threadIdx.x;
    int e = gid >> 3;
    int r = gid & 7;
    if (e >= EE) return;
    int s = ei[e];
    int d = ei[EE + e];
    float w = ew[e];
    int b = r >> 2;
    int q = r & 3;
    float4 wec = ((const float4*)s_we)[q];
    float sg0 = fsig(w * wec.x), sg1 = fsig(w * wec.y),
          sg2 = fsig(w * wec.z), sg3 = fsig(w * wec.w);
    float bl = s_sc[1] + w * s_sc[0];
    float2 kiv = *(const float2*)(g_ki1 + (size_t)d * BB);
    float2 qjv = *(const float2*)(g_qj1 + (size_t)s * BB);
    float att = fsig(bl + (b ? kiv.y : kiv.x) + (b ? qjv.y : qjv.x));
    float4 xj = ((const float4*)(g_xs1 + (size_t)s * (BB * SP_CH)))[r];
    red4(g_agg1 + (size_t)d * (BB * SP_CH) + 4 * r,
         att * sg0 * xj.x, att * sg1 * xj.y,
         att * sg2 * xj.z, att * sg3 * xj.w);
}

// ---------------- upd1 + node2 fused: one thread per (n,b) row ---------------
__global__ __launch_bounds__(256) void updnode2_kernel(const int* __restrict__ rn,
                                                       const float* __restrict__ cw,
                                                       const float* __restrict__ cb,
                                                       const float* __restrict__ value2) {
    __shared__ float s_w[32 * 16];
    __shared__ float s_b[16];
    __shared__ float s_v2[SP_CH * OUT_CH];
    __shared__ float s_ka[32], s_qa[32];
    for (int i = threadIdx.x; i < 512; i += blockDim.x) {
        s_w[i] = cw[i];
        s_v2[i] = value2[i];
    }
    if (threadIdx.x < 16) s_b[threadIdx.x] = cb[threadIdx.x];
    if (threadIdx.x < 32) {
        s_ka[threadIdx.x] = g_wder[48 + threadIdx.x];
        s_qa[threadIdx.x] = g_wder[80 + threadIdx.x];
    }
    __syncthreads();
    int t = blockIdx.x * blockDim.x + threadIdx.x;
    if (t >= NBN) return;
    int n = t / BB;
    int b = t - n * BB;
    int src = rn[n];
    const float4* px = (const float4*)(g_xs1 + ((size_t)src * BB + b) * SP_CH);
    const float4* pa = (const float4*)(g_agg1 + (size_t)t * SP_CH);
    float xd[16];
#pragma unroll
    for (int k = 0; k < 4; k++) {
        float4 v = px[k];
        xd[4 * k] = v.x; xd[4 * k + 1] = v.y; xd[4 * k + 2] = v.z; xd[4 * k + 3] = v.w;
    }
    float u[16];
#pragma unroll
    for (int c = 0; c < 16; c++) u[c] = s_b[c];
#pragma unroll
    for (int j = 0; j < 16; j++) {
#pragma unroll
        for (int c = 0; c < 16; c++) u[c] += xd[j] * s_w[j * 16 + c];
    }
#pragma unroll
    for (int k = 0; k < 4; k++) {
        float4 a = pa[k];
#pragma unroll
        for (int c = 0; c < 16; c++) {
            u[c] += a.x * s_w[(16 + 4 * k + 0) * 16 + c];
            u[c] += a.y * s_w[(16 + 4 * k + 1) * 16 + c];
            u[c] += a.z * s_w[(16 + 4 * k + 2) * 16 + c];
            u[c] += a.w * s_w[(16 + 4 * k + 3) * 16 + c];
        }
    }
    float x1[16];
#pragma unroll
    for (int c = 0; c < 16; c++) {
        float v = xd[c] + fmaxf(u[c], 0.f);
        x1[c] = v > 0.f ? v : 0.01f * v;  // leaky_relu
    }
    float acc[OUT_CH];
#pragma unroll
    for (int c = 0; c < OUT_CH; c++) acc[c] = 0.f;
#pragma unroll
    for (int j = 0; j < SP_CH; j++) {
#pragma unroll
        for (int c = 0; c < OUT_CH; c++) acc[c] += x1[j] * s_v2[j * OUT_CH + c];
    }
    float4* o = (float4*)(g_xs2 + (size_t)t * OUT_CH);
    float4* az = (float4*)(g_agg2 + (size_t)t * OUT_CH);
    float4 z = make_float4(0.f, 0.f, 0.f, 0.f);
    float qj = 0.f, ks = 0.f;
#pragma unroll
    for (int k = 0; k < 8; k++) {
        o[k] = make_float4(acc[4 * k], acc[4 * k + 1], acc[4 * k + 2], acc[4 * k + 3]);
        az[k] = z;
#pragma unroll
        for (int j = 0; j < 4; j++) {
            qj += acc[4 * k + j] * s_qa[4 * k + j];
            ks += acc[4 * k + j] * s_ka[4 * k + j];
        }
    }
    g_qj2[t] = qj;
    g_ks2[t] = ks;
}

// ---------------- pre2: scalar gather ----------------------------------------
__global__ __launch_bounds__(256) void pre2_kernel(const int* __restrict__ rn) {
    int n = blockIdx.x * blockDim.x + threadIdx.x;
    if (n >= NN) return;
    int src = rn[n];
    *(float2*)(g_ki2 + (size_t)n * BB) = *(const float2*)(g_ks2 + (size_t)src * BB);
}

// ---------------- edge2: 8 lanes per edge ------------------------------------
__global__ __launch_bounds__(256) void edge2_kernel(const int* __restrict__ ei,
                                                    const float* __restrict__ ew,
                                                    const float* __restrict__ we,
                                                    const float* __restrict__ attb) {
    __shared__ float s_we[32], s_sc[2];
    if (threadIdx.x < 32) s_we[threadIdx.x] = we[threadIdx.x];
    if (threadIdx.x == 0) { s_sc[0] = g_wder[112]; s_sc[1] = attb[0]; }
    __syncthreads();
    int gid = blockIdx.x * blockDim.x + threadIdx.x;
    int e = gid >> 3;
    int r = gid & 7;
    if (e >= EE) return;
    int s = ei[e];
    int d = ei[EE + e];
    float w = ew[e];
    float4 wec = ((const float4*)s_we)[r];
    float sg0 = fsig(w * wec.x), sg1 = fsig(w * wec.y),
          sg2 = fsig(w * wec.z), sg3 = fsig(w * wec.w);
    float bl = s_sc[1] + w * s_sc[0];
    float2 ki = *(const float2*)(g_ki2 + (size_t)d * BB);
    float2 qj = *(const float2*)(g_qj2 + (size_t)s * BB);
    float att0 = fsig(bl + ki.x + qj.x);
    float att1 = fsig(bl + ki.y + qj.y);
    const float4* xsrow = (const float4*)(g_xs2 + (size_t)s * BB * OUT_CH);
    float* aggrow = g_agg2 + (size_t)d * BB * OUT_CH;
    {
        float4 xj = xsrow[r];
        red4(aggrow + 4 * r,
             att0 * sg0 * xj.x, att0 * sg1 * xj.y,
             att0 * sg2 * xj.z, att0 * sg3 * xj.w);
    }
    {
        float4 xj = xsrow[8 + r];
        red4(aggrow + OUT_CH + 4 * r,
             att1 * sg0 * xj.x, att1 * sg1 * xj.y,
             att1 * sg2 * xj.z, att1 * sg3 * xj.w);
    }
}

// ---------------- upd2: one thread per (n,b); output [b][n][32] --------------
__global__ __launch_bounds__(256) void upd2_kernel(const int* __restrict__ rn,
                                                   const float* __restrict__ cw,
                                                   const float* __restrict__ cb,
                                                   float* __restrict__ out) {
    __shared__ float s_w[64 * 32];  // 8KB
    __shared__ float s_b[32];
    for (int i = threadIdx.x; i < 2048; i += blockDim.x) s_w[i] = cw[i];
    if (threadIdx.x < 32) s_b[threadIdx.x] = cb[threadIdx.x];
    __syncthreads();
    int t = blockIdx.x * blockDim.x + threadIdx.x;
    if (t >= NBN) return;
    int n = t / BB;
    int b = t - n * BB;
    int src = rn[n];
    const float4* px = (const float4*)(g_xs2 + ((size_t)src * BB + b) * OUT_CH);
    const float4* pa = (const float4*)(g_agg2 + (size_t)t * OUT_CH);
    float xd[32];
#pragma unroll
    for (int k = 0; k < 8; k++) {
        float4 v = px[k];
        xd[4 * k] = v.x; xd[4 * k + 1] = v.y; xd[4 * k + 2] = v.z; xd[4 * k + 3] = v.w;
    }
    float u[32];
#pragma unroll
    for (int c = 0; c < 32; c++) u[c] = s_b[c];
#pragma unroll 8
    for (int j = 0; j < 32; j++) {
#pragma unroll
        for (int c = 0; c < 32; c++) u[c] += xd[j] * s_w[j * 32 + c];
    }
#pragma unroll
    for (int k = 0; k < 8; k++) {
        float4 a = pa[k];
#pragma unroll
        for (int c = 0; c < 32; c++) {
            u[c] += a.x * s_w[(32 + 4 * k + 0) * 32 + c];
            u[c] += a.y * s_w[(32 + 4 * k + 1) * 32 + c];
            u[c] += a.z * s_w[(32 + 4 * k + 2) * 32 + c];
            u[c] += a.w * s_w[(32 + 4 * k + 3) * 32 + c];
        }
    }
    float4* o = (float4*)(out + ((size_t)b * NN + n) * OUT_CH);
#pragma unroll
    for (int k = 0; k < 8; k++) {
        float r0 = xd[4 * k + 0] + fmaxf(u[4 * k + 0], 0.f);
        float r1 = xd[4 * k + 1] + fmaxf(u[4 * k + 1], 0.f);
        float r2 = xd[4 * k + 2] + fmaxf(u[4 * k + 2], 0.f);
        float r3 = xd[4 * k + 3] + fmaxf(u[4 * k + 3], 0.f);
        o[k] = make_float4(r0, r1, r2, r3);
    }
}

// ---------------- launch -----------------------------------------------------
extern "C" void kernel_launch(void* const* d_in, const int* in_sizes, int n_in,
                              void* d_out, int out_size) {
    const float* X      = (const float*)d_in[0];
    const int*   ei0    = (const int*)d_in[1];
    const int*   ei1    = (const int*)d_in[2];
    const float* ew0    = (const float*)d_in[3];
    const float* ew1    = (const float*)d_in[4];
    const int*   rn0    = (const int*)d_in[5];
    const int*   rn1    = (const int*)d_in[6];
    const float* value1 = (const float*)d_in[7];
    const float* key1   = (const float*)d_in[8];
    const float* query1 = (const float*)d_in[9];
    const float* we1    = (const float*)d_in[10];
    const float* attw1  = (const float*)d_in[11];
    const float* attb1  = (const float*)d_in[12];
    const float* catw1  = (const float*)d_in[13];
    const float* catb1  = (const float*)d_in[14];
    const float* value2 = (const float*)d_in[15];
    const float* key2   = (const float*)d_in[16];
    const float* query2 = (const float*)d_in[17];
    const float* we2    = (const float*)d_in[18];
    const float* attw2  = (const float*)d_in[19];
    const float* attb2  = (const float*)d_in[20];
    const float* catw2  = (const float*)d_in[21];
    const float* catb2  = (const float*)d_in[22];
    float* out = (float*)d_out;

    const int rowBlocks   = (NBN + 255) / 256;
    const int nBlocks     = (NN + 255) / 256;
    const int edgeBlocks8 = (EE * 8 + 255) / 256;

    prep_kernel<<<1, 64>>>(key1, query1, we1, attw1, key2, query2, we2, attw2);
    node1_kernel<<<rowBlocks, 256>>>(X, value1);
    pre1_kernel<<<nBlocks, 256>>>(rn0);
    edge1_kernel<<<edgeBlocks8, 256>>>(ei0, ew0, we1, attb1);
    updnode2_kernel<<<rowBlocks, 256>>>(rn0, catw1, catb1, value2);
    pre2_kernel<<<nBlocks, 256>>>(rn1);
    edge2_kernel<<<edgeBlocks8, 256>>>(ei1, ew1, we2, attb2);
    upd2_kernel<<<rowBlocks, 256>>>(rn1, catw2, catb2, out);
}